// round 2
// baseline (speedup 1.0000x reference)
#include <cuda_runtime.h>
#include <cuda_fp16.h>
#include <cstdint>

// ---------------------------------------------------------------------------
// out[8192,4096] = x[8192,4096]_fp32 @ sign(fp16(w[4096,4096]))
//
// Build target is plain sm_103 (no 'a' suffix) => tcgen05/TMEM unavailable.
// Use the arch-portable tensor-core path: cp.async + ldmatrix +
// mma.sync.m16n8k16.f32.f16.f16.f32.
//
// Phase 1: convert x -> fp16 (g_xh, [M,K] row-major)
//          convert w -> sign(fp16(w)) as fp16, transposed (g_wbt, [N,K])
// Phase 2: pipelined 128x128x64 GEMM, fp32 accum.
// ---------------------------------------------------------------------------

#define M_DIM 8192
#define N_DIM 4096
#define K_DIM 4096

#define BM 128
#define BN 128
#define BK 64
#define STAGES 3
#define THREADS 256

#define A_TILE_BYTES (BM * BK * 2)            // 16384
#define B_TILE_BYTES (BN * BK * 2)            // 16384
#define STAGE_BYTES  (A_TILE_BYTES + B_TILE_BYTES)
#define SMEM_DYN     (STAGES * STAGE_BYTES)   // 98304

// ------------------------------ scratch -----------------------------------
__device__ __align__(1024) __half g_xh[(size_t)M_DIM * K_DIM];   // 64 MB
__device__ __align__(1024) __half g_wbt[(size_t)N_DIM * K_DIM];  // 32 MB

// --------------------------- convert kernels -------------------------------
__global__ void cvt_x_kernel(const float4* __restrict__ x, uint2* __restrict__ xh, int n4) {
    int i = blockIdx.x * blockDim.x + threadIdx.x;
    if (i >= n4) return;
    float4 v = x[i];
    __half2 a = __floats2half2_rn(v.x, v.y);
    __half2 b = __floats2half2_rn(v.z, v.w);
    uint2 o;
    o.x = *reinterpret_cast<uint32_t*>(&a);
    o.y = *reinterpret_cast<uint32_t*>(&b);
    xh[i] = o;
}

// w[K,N] fp32 -> wbt[N,K] fp16 with value sign(fp16(w)) (sign(0) = 0)
__global__ void cvt_w_kernel(const float* __restrict__ w, __half* __restrict__ wbt) {
    __shared__ __half tile[32][33];
    int n0 = blockIdx.x * 32;
    int k0 = blockIdx.y * 32;
    int tx = threadIdx.x, ty = threadIdx.y;
    #pragma unroll
    for (int j = ty; j < 32; j += 8) {
        float v = w[(size_t)(k0 + j) * N_DIM + n0 + tx];
        float hf = __half2float(__float2half_rn(v));  // exact fp16 round trip
        float s = (hf > 0.f) ? 1.f : ((hf < 0.f) ? -1.f : 0.f);
        tile[j][tx] = __float2half_rn(s);
    }
    __syncthreads();
    #pragma unroll
    for (int j = ty; j < 32; j += 8) {
        wbt[(size_t)(n0 + j) * K_DIM + k0 + tx] = tile[tx][j];
    }
}

// ------------------------------ PTX helpers -------------------------------
__device__ __forceinline__ uint32_t smem_u32(const void* p) {
    uint32_t a;
    asm("{ .reg .u64 t; cvta.to.shared.u64 t, %1; cvt.u32.u64 %0, t; }"
        : "=r"(a) : "l"(p));
    return a;
}

__device__ __forceinline__ void cp_async_16(uint32_t smem_dst, const void* gmem_src) {
    asm volatile("cp.async.cg.shared.global [%0], [%1], 16;"
                 :: "r"(smem_dst), "l"(gmem_src));
}
__device__ __forceinline__ void cp_commit() {
    asm volatile("cp.async.commit_group;" ::: "memory");
}
template <int N>
__device__ __forceinline__ void cp_wait() {
    asm volatile("cp.async.wait_group %0;" :: "n"(N) : "memory");
}

__device__ __forceinline__ void ldmatrix_x4(uint32_t& r0, uint32_t& r1,
                                            uint32_t& r2, uint32_t& r3, uint32_t addr) {
    asm volatile("ldmatrix.sync.aligned.m8n8.x4.shared.b16 {%0,%1,%2,%3}, [%4];"
                 : "=r"(r0), "=r"(r1), "=r"(r2), "=r"(r3) : "r"(addr));
}

__device__ __forceinline__ void mma_16816(float* c, const uint32_t* a, const uint32_t* b) {
    asm volatile(
        "mma.sync.aligned.m16n8k16.row.col.f32.f16.f16.f32 "
        "{%0,%1,%2,%3}, {%4,%5,%6,%7}, {%8,%9}, {%0,%1,%2,%3};"
        : "+f"(c[0]), "+f"(c[1]), "+f"(c[2]), "+f"(c[3])
        : "r"(a[0]), "r"(a[1]), "r"(a[2]), "r"(a[3]), "r"(b[0]), "r"(b[1]));
}

// SW128-style swizzle within a [rows][BK] fp16 tile with 128B row stride:
// chunk (16B unit, 0..7) XOR'd with (row & 7).
__device__ __forceinline__ uint32_t tile_off(int row, int chunk) {
    return (uint32_t)(row * 128 + ((chunk ^ (row & 7)) << 4));
}

// ------------------------------ GEMM kernel --------------------------------
__global__ void __launch_bounds__(THREADS, 1) bgemm_mma_kernel(
    const __half* __restrict__ A,   // [M,K]
    const __half* __restrict__ B,   // [N,K]
    float* __restrict__ out)
{
    extern __shared__ uint8_t smem_raw[];
    const uint32_t smem = smem_u32(smem_raw);

    const int tid  = threadIdx.x;
    const int wid  = tid >> 5;
    const int lane = tid & 31;
    const int m0 = blockIdx.x * BM;
    const int n0 = blockIdx.y * BN;

    const int warp_m = wid & 3;   // 4 warps over M: 32 rows each
    const int warp_n = wid >> 2;  // 2 warps over N: 64 cols each

    // --- cp.async load mapping: 256 threads x 16B; tile = 128 rows x 8 chunks
    // pass p: id = p*256 + tid; row = id/8, chunk = id%8 (2 passes per tile)
    const int ld_row0 = tid >> 3;        // 0..31
    const int ld_chunk = tid & 7;        // 0..7

    auto load_stage = [&](int slot, int kt) {
        const uint32_t sA = smem + slot * STAGE_BYTES;
        const uint32_t sB = sA + A_TILE_BYTES;
        const int kcol = kt * BK + ld_chunk * 8;
        #pragma unroll
        for (int p = 0; p < 4; p++) {
            int row = ld_row0 + p * 32;
            cp_async_16(sA + tile_off(row, ld_chunk),
                        A + (size_t)(m0 + row) * K_DIM + kcol);
            cp_async_16(sB + tile_off(row, ld_chunk),
                        B + (size_t)(n0 + row) * K_DIM + kcol);
        }
        cp_commit();
    };

    const int NK = K_DIM / BK;  // 64

    // prologue: stages 0..STAGES-2
    #pragma unroll
    for (int s = 0; s < STAGES - 1; s++) load_stage(s, s);

    float acc[2][8][4];
    #pragma unroll
    for (int mi = 0; mi < 2; mi++)
        #pragma unroll
        for (int ni = 0; ni < 8; ni++)
            #pragma unroll
            for (int j = 0; j < 4; j++) acc[mi][ni][j] = 0.f;

    const int lrow = lane & 15;    // ldmatrix row within 16
    const int lsel = lane >> 4;    // ldmatrix chunk select (0/1)

    for (int it = 0; it < NK; it++) {
        cp_wait<STAGES - 2>();
        __syncthreads();

        const int ls = it + STAGES - 1;
        if (ls < NK) load_stage(ls % STAGES, ls);

        const int slot = it % STAGES;
        const uint32_t sA = smem + slot * STAGE_BYTES;
        const uint32_t sB = sA + A_TILE_BYTES;

        #pragma unroll
        for (int kk = 0; kk < BK / 16; kk++) {          // 4 k16 steps
            const int chunk = kk * 2 + lsel;

            uint32_t a[2][4];
            #pragma unroll
            for (int mi = 0; mi < 2; mi++) {
                int row = warp_m * 32 + mi * 16 + lrow;
                ldmatrix_x4(a[mi][0], a[mi][1], a[mi][2], a[mi][3],
                            sA + tile_off(row, chunk));
            }
            uint32_t b[8][2];
            #pragma unroll
            for (int nj = 0; nj < 4; nj++) {            // each x4 -> 2 n-frags
                int row = warp_n * 64 + nj * 16 + lrow;
                uint32_t r0, r1, r2, r3;
                ldmatrix_x4(r0, r1, r2, r3, sB + tile_off(row, chunk));
                b[nj * 2 + 0][0] = r0; b[nj * 2 + 1][0] = r1;
                b[nj * 2 + 0][1] = r2; b[nj * 2 + 1][1] = r3;
            }
            #pragma unroll
            for (int mi = 0; mi < 2; mi++)
                #pragma unroll
                for (int ni = 0; ni < 8; ni++)
                    mma_16816(acc[mi][ni], a[mi], b[ni]);
        }
        __syncthreads();
    }

    // ------------------------------ epilogue -------------------------------
    const int tq = lane >> 2;       // 0..7 (row within 8)
    const int tp = lane & 3;        // col pair
    #pragma unroll
    for (int mi = 0; mi < 2; mi++) {
        #pragma unroll
        for (int ni = 0; ni < 8; ni++) {
            int r = m0 + warp_m * 32 + mi * 16 + tq;
            int c = n0 + warp_n * 64 + ni * 8 + tp * 2;
            float2 v0 = make_float2(acc[mi][ni][0], acc[mi][ni][1]);
            float2 v1 = make_float2(acc[mi][ni][2], acc[mi][ni][3]);
            *reinterpret_cast<float2*>(out + (size_t)r * N_DIM + c) = v0;
            *reinterpret_cast<float2*>(out + (size_t)(r + 8) * N_DIM + c) = v1;
        }
    }
}

// ------------------------------- host side --------------------------------
extern "C" void kernel_launch(void* const* d_in, const int* in_sizes, int n_in,
                              void* d_out, int out_size)
{
    const float* x = (const float*)d_in[0];
    const float* w = (const float*)d_in[1];
    float* out = (float*)d_out;

    void *xh_ptr = nullptr, *wbt_ptr = nullptr;
    cudaGetSymbolAddress(&xh_ptr, g_xh);
    cudaGetSymbolAddress(&wbt_ptr, g_wbt);

    {
        int n4 = (M_DIM * K_DIM) / 4;
        cvt_x_kernel<<<(n4 + 255) / 256, 256>>>((const float4*)x, (uint2*)xh_ptr, n4);
        dim3 gw(N_DIM / 32, K_DIM / 32), bw(32, 8);
        cvt_w_kernel<<<gw, bw>>>(w, (__half*)wbt_ptr);
    }

    static bool attr_set = false;  // idempotent attribute set (not a work guard)
    cudaFuncSetAttribute(bgemm_mma_kernel,
                         cudaFuncAttributeMaxDynamicSharedMemorySize, SMEM_DYN);
    (void)attr_set;

    dim3 grid(M_DIM / BM, N_DIM / BN);  // (64, 32)
    bgemm_mma_kernel<<<grid, THREADS, SMEM_DYN>>>(
        (const __half*)xh_ptr, (const __half*)wbt_ptr, out);
}

// round 3
// speedup vs baseline: 1.0074x; 1.0074x over previous
#include <cuda_runtime.h>
#include <cuda_fp16.h>
#include <cstdint>

// ---------------------------------------------------------------------------
// out[8192,4096] = x[8192,4096]_fp32 @ sign(fp16(w[4096,4096]))
//
// Build target is plain sm_103 => tcgen05/TMEM unavailable; use the portable
// tensor-core path: cp.async + ldmatrix + mma.sync.m16n8k16.f32.f16.f16.f32.
//
// R3: 4-stage pipeline, register double-buffered fragments with cross-slot
// prefetch, single barrier per k-iteration.
// ---------------------------------------------------------------------------

#define M_DIM 8192
#define N_DIM 4096
#define K_DIM 4096

#define BM 128
#define BN 128
#define BK 64
#define STAGES 4
#define THREADS 256
#define NKI (K_DIM / BK)   // 64

#define A_TILE_BYTES (BM * BK * 2)            // 16384
#define B_TILE_BYTES (BN * BK * 2)            // 16384
#define STAGE_BYTES  (A_TILE_BYTES + B_TILE_BYTES)
#define SMEM_DYN     (STAGES * STAGE_BYTES)   // 131072

// ------------------------------ scratch -----------------------------------
__device__ __align__(1024) __half g_xh[(size_t)M_DIM * K_DIM];   // 64 MB
__device__ __align__(1024) __half g_wbt[(size_t)N_DIM * K_DIM];  // 32 MB

// --------------------------- convert kernels -------------------------------
__global__ void cvt_x_kernel(const float4* __restrict__ x, uint2* __restrict__ xh, int n4) {
    int i = blockIdx.x * blockDim.x + threadIdx.x;
    if (i >= n4) return;
    float4 v = x[i];
    __half2 a = __floats2half2_rn(v.x, v.y);
    __half2 b = __floats2half2_rn(v.z, v.w);
    uint2 o;
    o.x = *reinterpret_cast<uint32_t*>(&a);
    o.y = *reinterpret_cast<uint32_t*>(&b);
    xh[i] = o;
}

// w[K,N] fp32 -> wbt[N,K] fp16 with value sign(fp16(w)) (sign(0) = 0)
__global__ void cvt_w_kernel(const float* __restrict__ w, __half* __restrict__ wbt) {
    __shared__ __half tile[32][33];
    int n0 = blockIdx.x * 32;
    int k0 = blockIdx.y * 32;
    int tx = threadIdx.x, ty = threadIdx.y;
    #pragma unroll
    for (int j = ty; j < 32; j += 8) {
        float v = w[(size_t)(k0 + j) * N_DIM + n0 + tx];
        float hf = __half2float(__float2half_rn(v));  // exact fp16 round trip
        float s = (hf > 0.f) ? 1.f : ((hf < 0.f) ? -1.f : 0.f);
        tile[j][tx] = __float2half_rn(s);
    }
    __syncthreads();
    #pragma unroll
    for (int j = ty; j < 32; j += 8) {
        wbt[(size_t)(n0 + j) * K_DIM + k0 + tx] = tile[tx][j];
    }
}

// ------------------------------ PTX helpers -------------------------------
__device__ __forceinline__ uint32_t smem_u32(const void* p) {
    uint32_t a;
    asm("{ .reg .u64 t; cvta.to.shared.u64 t, %1; cvt.u32.u64 %0, t; }"
        : "=r"(a) : "l"(p));
    return a;
}

__device__ __forceinline__ void cp_async_16(uint32_t smem_dst, const void* gmem_src) {
    asm volatile("cp.async.cg.shared.global [%0], [%1], 16;"
                 :: "r"(smem_dst), "l"(gmem_src));
}
__device__ __forceinline__ void cp_commit() {
    asm volatile("cp.async.commit_group;" ::: "memory");
}
template <int N>
__device__ __forceinline__ void cp_wait() {
    asm volatile("cp.async.wait_group %0;" :: "n"(N) : "memory");
}

__device__ __forceinline__ void ldmatrix_x4(uint32_t& r0, uint32_t& r1,
                                            uint32_t& r2, uint32_t& r3, uint32_t addr) {
    asm volatile("ldmatrix.sync.aligned.m8n8.x4.shared.b16 {%0,%1,%2,%3}, [%4];"
                 : "=r"(r0), "=r"(r1), "=r"(r2), "=r"(r3) : "r"(addr));
}

__device__ __forceinline__ void mma_16816(float* c, const uint32_t* a, const uint32_t* b) {
    asm volatile(
        "mma.sync.aligned.m16n8k16.row.col.f32.f16.f16.f32 "
        "{%0,%1,%2,%3}, {%4,%5,%6,%7}, {%8,%9}, {%0,%1,%2,%3};"
        : "+f"(c[0]), "+f"(c[1]), "+f"(c[2]), "+f"(c[3])
        : "r"(a[0]), "r"(a[1]), "r"(a[2]), "r"(a[3]), "r"(b[0]), "r"(b[1]));
}

// SW128-style swizzle within a [rows][BK] fp16 tile with 128B row stride:
// chunk (16B unit, 0..7) XOR'd with (row & 7).
__device__ __forceinline__ uint32_t tile_off(int row, int chunk) {
    return (uint32_t)(row * 128 + ((chunk ^ (row & 7)) << 4));
}

// ------------------------------ GEMM kernel --------------------------------
__global__ void __launch_bounds__(THREADS, 1) bgemm_mma_kernel(
    const __half* __restrict__ A,   // [M,K]
    const __half* __restrict__ B,   // [N,K]
    float* __restrict__ out)
{
    extern __shared__ uint8_t smem_raw[];
    const uint32_t smem = smem_u32(smem_raw);

    const int tid  = threadIdx.x;
    const int wid  = tid >> 5;
    const int lane = tid & 31;
    const int m0 = blockIdx.x * BM;
    const int n0 = blockIdx.y * BN;

    const int warp_m = wid & 3;   // 4 warps over M: 32 rows each
    const int warp_n = wid >> 2;  // 2 warps over N: 64 cols each

    // cp.async mapping: 256 threads x 16B; tile = 128 rows x 8 chunks, 4 passes
    const int ld_row0  = tid >> 3;   // 0..31
    const int ld_chunk = tid & 7;    // 0..7

    auto load_stage = [&](int slot, int kt) {
        const uint32_t sA = smem + slot * STAGE_BYTES;
        const uint32_t sB = sA + A_TILE_BYTES;
        const int kcol = kt * BK + ld_chunk * 8;
        #pragma unroll
        for (int p = 0; p < 4; p++) {
            int row = ld_row0 + p * 32;
            cp_async_16(sA + tile_off(row, ld_chunk),
                        A + (size_t)(m0 + row) * K_DIM + kcol);
            cp_async_16(sB + tile_off(row, ld_chunk),
                        B + (size_t)(n0 + row) * K_DIM + kcol);
        }
        cp_commit();
    };

    const int lrow = lane & 15;    // ldmatrix row within 16
    const int lsel = lane >> 4;    // ldmatrix chunk select (0/1)

    // fragment loader for one k16 step from a given stage base
    auto load_frags = [&](uint32_t sA, uint32_t sB, int kk,
                          uint32_t a[2][4], uint32_t b[8][2]) {
        const int chunk = kk * 2 + lsel;
        #pragma unroll
        for (int mi = 0; mi < 2; mi++) {
            int row = warp_m * 32 + mi * 16 + lrow;
            ldmatrix_x4(a[mi][0], a[mi][1], a[mi][2], a[mi][3],
                        sA + tile_off(row, chunk));
        }
        #pragma unroll
        for (int nj = 0; nj < 4; nj++) {
            int row = warp_n * 64 + nj * 16 + lrow;
            uint32_t r0, r1, r2, r3;
            ldmatrix_x4(r0, r1, r2, r3, sB + tile_off(row, chunk));
            b[nj * 2 + 0][0] = r0; b[nj * 2 + 1][0] = r1;
            b[nj * 2 + 0][1] = r2; b[nj * 2 + 1][1] = r3;
        }
    };

    float acc[2][8][4];
    #pragma unroll
    for (int mi = 0; mi < 2; mi++)
        #pragma unroll
        for (int ni = 0; ni < 8; ni++)
            #pragma unroll
            for (int j = 0; j < 4; j++) acc[mi][ni][j] = 0.f;

    // prologue: fill stages 0..2
    #pragma unroll
    for (int s = 0; s < STAGES - 1; s++) load_stage(s, s);
    cp_wait<1>();           // stages 0 and 1 resident
    __syncthreads();

    uint32_t af[2][2][4];
    uint32_t bf[2][8][2];
    {
        const uint32_t sA0 = smem;                // slot 0
        load_frags(sA0, sA0 + A_TILE_BYTES, 0, af[0], bf[0]);
    }

    for (int it = 0; it < NKI; it++) {
        // issue load for stage it+3 into slot (it+3)%4 (overwrites the slot
        // last read in iteration it-1; the barrier at end of it-1 covers it)
        if (it + STAGES - 1 < NKI) load_stage((it + STAGES - 1) & 3, it + STAGES - 1);

        const uint32_t sA  = smem + (it & 3) * STAGE_BYTES;
        const uint32_t sB  = sA + A_TILE_BYTES;
        // next-iteration slot (resident by the wait<1> invariant); at it=NKI-1
        // this reads stale-but-valid smem whose frags are never consumed.
        const uint32_t sAn = smem + ((it + 1) & 3) * STAGE_BYTES;
        const uint32_t sBn = sAn + A_TILE_BYTES;

        #pragma unroll
        for (int kk = 0; kk < BK / 16; kk++) {
            const int cur = kk & 1;
            const int nxt = cur ^ 1;
            if (kk < 3) {
                load_frags(sA, sB, kk + 1, af[nxt], bf[nxt]);
            } else {
                load_frags(sAn, sBn, 0, af[nxt], bf[nxt]);
            }
            #pragma unroll
            for (int mi = 0; mi < 2; mi++)
                #pragma unroll
                for (int ni = 0; ni < 8; ni++)
                    mma_16816(acc[mi][ni], af[cur][mi], bf[cur][ni]);
        }

        if (it + 1 < NKI) {
            cp_wait<1>();       // ensures stage it+2 resident for next iter
            __syncthreads();    // single barrier per k-iteration
        }
    }

    // ------------------------------ epilogue -------------------------------
    const int tq = lane >> 2;       // 0..7 (row within 8)
    const int tp = lane & 3;        // col pair
    #pragma unroll
    for (int mi = 0; mi < 2; mi++) {
        #pragma unroll
        for (int ni = 0; ni < 8; ni++) {
            int r = m0 + warp_m * 32 + mi * 16 + tq;
            int c = n0 + warp_n * 64 + ni * 8 + tp * 2;
            float2 v0 = make_float2(acc[mi][ni][0], acc[mi][ni][1]);
            float2 v1 = make_float2(acc[mi][ni][2], acc[mi][ni][3]);
            *reinterpret_cast<float2*>(out + (size_t)r * N_DIM + c) = v0;
            *reinterpret_cast<float2*>(out + (size_t)(r + 8) * N_DIM + c) = v1;
        }
    }
}

// ------------------------------- host side --------------------------------
extern "C" void kernel_launch(void* const* d_in, const int* in_sizes, int n_in,
                              void* d_out, int out_size)
{
    const float* x = (const float*)d_in[0];
    const float* w = (const float*)d_in[1];
    float* out = (float*)d_out;

    void *xh_ptr = nullptr, *wbt_ptr = nullptr;
    cudaGetSymbolAddress(&xh_ptr, g_xh);
    cudaGetSymbolAddress(&wbt_ptr, g_wbt);

    {
        int n4 = (M_DIM * K_DIM) / 4;
        cvt_x_kernel<<<(n4 + 255) / 256, 256>>>((const float4*)x, (uint2*)xh_ptr, n4);
        dim3 gw(N_DIM / 32, K_DIM / 32), bw(32, 8);
        cvt_w_kernel<<<gw, bw>>>(w, (__half*)wbt_ptr);
    }

    cudaFuncSetAttribute(bgemm_mma_kernel,
                         cudaFuncAttributeMaxDynamicSharedMemorySize, SMEM_DYN);

    dim3 grid(M_DIM / BM, N_DIM / BN);  // (64, 32)
    bgemm_mma_kernel<<<grid, THREADS, SMEM_DYN>>>(
        (const __half*)xh_ptr, (const __half*)wbt_ptr, out);
}